// round 6
// baseline (speedup 1.0000x reference)
#include <cuda_runtime.h>
#include <cuda_fp16.h>
#include <cstdint>

#define L_Q   4096
#define L_CTX 4097
#define C_DIM 320
#define N_HEADS 8
#define DHEAD 40
#define DPAD  48
#define WSZ   (C_DIM * C_DIM)   // 102400

// ---------------- device scratch (no allocations allowed) ----------------
__device__ __half g_ctx_h[(size_t)L_CTX * C_DIM];   // context hi fp16
__device__ __half g_ctx_l[(size_t)L_CTX * C_DIM];   // context lo fp16 (residual)
__device__ __half g_w_h[4 * WSZ];                   // Wq,Wk,Wv,Wo hi
__device__ __half g_w_l[4 * WSZ];                   // Wq,Wk,Wv,Wo lo
__device__ __half g_q[(size_t)N_HEADS * L_Q * DPAD];    // d 40..47 stay zero
__device__ __half g_k[(size_t)N_HEADS * L_CTX * DPAD];
__device__ __half g_v[(size_t)N_HEADS * L_CTX * DPAD];
__device__ __half g_oh[(size_t)L_Q * C_DIM];        // attention out hi
__device__ __half g_ol[(size_t)L_Q * C_DIM];        // attention out lo
__device__ unsigned g_mbits[L_Q * 128];             // packed mask bits
__device__ int    g_mask_is_u8;

#define LOG2E 1.4426950408889634f

// ---------------- mma / ldmatrix helpers ----------------
__device__ __forceinline__ void mma16816(float* d, const uint32_t* a, const uint32_t* b) {
    asm volatile(
        "mma.sync.aligned.m16n8k16.row.col.f32.f16.f16.f32 "
        "{%0,%1,%2,%3}, {%4,%5,%6,%7}, {%8,%9}, {%0,%1,%2,%3};"
        : "+f"(d[0]), "+f"(d[1]), "+f"(d[2]), "+f"(d[3])
        : "r"(a[0]), "r"(a[1]), "r"(a[2]), "r"(a[3]), "r"(b[0]), "r"(b[1]));
}
__device__ __forceinline__ void ldsm4(uint32_t* r, uint32_t saddr) {
    asm volatile("ldmatrix.sync.aligned.m8n8.x4.shared.b16 {%0,%1,%2,%3}, [%4];"
                 : "=r"(r[0]), "=r"(r[1]), "=r"(r[2]), "=r"(r[3]) : "r"(saddr));
}
__device__ __forceinline__ void ldsm2t(uint32_t* r, uint32_t saddr) {
    asm volatile("ldmatrix.sync.aligned.m8n8.x2.trans.shared.b16 {%0,%1}, [%2];"
                 : "=r"(r[0]), "=r"(r[1]) : "r"(saddr));
}
__device__ __forceinline__ uint32_t pack_half2(float lo, float hi) {
    __half2 h = __floats2half2_rn(lo, hi);
    return *(uint32_t*)&h;
}
__device__ __forceinline__ void split_h(float v, __half& h, __half& l) {
    h = __float2half_rn(v);
    l = __float2half_rn(v - __half2float(h));
}
__device__ __forceinline__ float ex2(float x) {
    float y;
    asm("ex2.approx.f32 %0, %1;" : "=f"(y) : "f"(x));
    return y;
}

// ---------------- kernel 0: detect mask dtype ----------------
__global__ void detect_mask_kernel(const unsigned char* __restrict__ mask) {
    __shared__ int cnt[256];
    int tid = threadIdx.x;
    int c = 0;
    for (int i = tid; i < 4096; i += 256) c += (mask[i] != 0);
    cnt[tid] = c;
    __syncthreads();
    for (int s = 128; s; s >>= 1) {
        if (tid < s) cnt[tid] += cnt[tid + s];
        __syncthreads();
    }
    if (tid == 0) g_mask_is_u8 = (cnt[0] > 1024) ? 1 : 0;
}

// ---------------- kernel 0b: pack mask to bits ----------------
__global__ void pack_mask_kernel(const void* __restrict__ mask) {
    int idx = blockIdx.x * 256 + threadIdx.x;
    int v = g_mask_is_u8 ? (int)((const unsigned char*)mask)[idx]
                         : ((const int*)mask)[idx];
    unsigned bal = __ballot_sync(0xffffffffu, v != 0);
    if ((threadIdx.x & 31) == 0) g_mbits[idx >> 5] = bal;
}

// ---------------- kernel 0c: split weights to fp16 hi/lo ----------------
__global__ void split_w_kernel(const float* __restrict__ Wq, const float* __restrict__ Wk,
                               const float* __restrict__ Wv, const float* __restrict__ Wo) {
    int which = blockIdx.y;
    const float* W = (which == 0) ? Wq : (which == 1) ? Wk : (which == 2) ? Wv : Wo;
    int idx = blockIdx.x * 256 + threadIdx.x;
    float v = W[idx];
    __half h, l;
    split_h(v, h, l);
    g_w_h[which * WSZ + idx] = h;
    g_w_l[which * WSZ + idx] = l;
}

// ---------------- kernel 1: build context, transposed, split fp16 ----------------
__global__ void build_ctx_kernel(const float* __restrict__ feat,
                                 const float* __restrict__ reg) {
    __shared__ float tile[32][33];
    int c0 = blockIdx.x * 32, x0 = blockIdx.y * 32, t = blockIdx.z;
    if (blockIdx.x == 0 && blockIdx.y == 0 && t == 0) {
        int lt = threadIdx.y * 32 + threadIdx.x;
        for (int c = lt; c < C_DIM; c += 256) {
            __half h, l;
            split_h(reg[c], h, l);
            g_ctx_h[c] = h;
            g_ctx_l[c] = l;
        }
    }
#pragma unroll
    for (int j = 0; j < 32; j += 8)
        tile[threadIdx.y + j][threadIdx.x] =
            feat[((size_t)(t * C_DIM + c0 + threadIdx.y + j)) * 256 + x0 + threadIdx.x];
    __syncthreads();
#pragma unroll
    for (int j = 0; j < 32; j += 8) {
        float v = tile[threadIdx.x][threadIdx.y + j];
        __half h, l;
        split_h(v, h, l);
        size_t off = (size_t)(1 + t * 256 + x0 + threadIdx.y + j) * C_DIM + c0 + threadIdx.x;
        g_ctx_h[off] = h;
        g_ctx_l[off] = l;
    }
}

// ---------------- kernel 2: fused QKV projection, fp16 HMMA, k-chunk 32 ----------------
// grid (33, 15): x = 128-row tile, y: z=y/5 selects Q/K/V, (y%5)*64 = col tile.
__global__ void __launch_bounds__(256) qkv_hmma_kernel() {
    __shared__ __half sAh[128 * 40], sAl[128 * 40];
    __shared__ __half sBh[32 * 72],  sBl[32 * 72];

    int by = blockIdx.y;
    int z = by / 5;
    int rows = (z == 0) ? L_Q : L_CTX;
    int ashift = (z == 0) ? 1 : 0;
    int row0 = blockIdx.x * 128;
    if (row0 >= rows) return;
    int ncol0 = (by % 5) * 64;

    int tid = threadIdx.x;
    int w = tid >> 5, lane = tid & 31;
    int g = lane >> 2, qc = lane & 3;
    int wrow = w * 16;

    uint32_t sAhb = (uint32_t)__cvta_generic_to_shared(sAh);
    uint32_t sAlb = (uint32_t)__cvta_generic_to_shared(sAl);
    uint32_t sBhb = (uint32_t)__cvta_generic_to_shared(sBh);
    uint32_t sBlb = (uint32_t)__cvta_generic_to_shared(sBl);

    float acc[8][4] = {};

    for (int k0 = 0; k0 < C_DIM; k0 += 32) {
        __syncthreads();
        // A tile: 128 rows x 32 k (hi+lo): 512 uint4 -> 2 iters x 256 threads
#pragma unroll
        for (int i = 0; i < 2; i++) {
            int id = tid + i * 256;
            int r = id >> 2, c = (id & 3) * 8;
            uint4 vh = make_uint4(0, 0, 0, 0), vl = vh;
            if (row0 + r < rows) {
                size_t off = (size_t)(row0 + r + ashift) * C_DIM + k0 + c;
                vh = *(const uint4*)&g_ctx_h[off];
                vl = *(const uint4*)&g_ctx_l[off];
            }
            *(uint4*)&sAh[r * 40 + c] = vh;
            *(uint4*)&sAl[r * 40 + c] = vl;
        }
        // B tile: 32 k x 64 n = 256 uint4 -> exactly 256 threads, one pass
        {
            int r = tid >> 3, c = (tid & 7) * 8;
            size_t off = (size_t)z * WSZ + (size_t)(k0 + r) * C_DIM + ncol0 + c;
            *(uint4*)&sBh[r * 72 + c] = *(const uint4*)&g_w_h[off];
            *(uint4*)&sBl[r * 72 + c] = *(const uint4*)&g_w_l[off];
        }
        __syncthreads();

#pragma unroll
        for (int kk = 0; kk < 2; kk++) {
            uint32_t ah[4], al[4];
            uint32_t aoff = (uint32_t)(((wrow + (lane & 15)) * 40 + kk * 16 + ((lane >> 4) << 3)) * 2);
            ldsm4(ah, sAhb + aoff);
            ldsm4(al, sAlb + aoff);
#pragma unroll
            for (int nt = 0; nt < 8; nt++) {
                uint32_t bh[2], bl[2];
                uint32_t boff = (uint32_t)(((kk * 16 + (lane & 15)) * 72 + nt * 8) * 2);
                ldsm2t(bh, sBhb + boff);
                ldsm2t(bl, sBlb + boff);
                mma16816(acc[nt], ah, bh);
                mma16816(acc[nt], ah, bl);
                mma16816(acc[nt], al, bh);
            }
        }
    }

    // epilogue: Q gets softmax scale * log2(e) folded in
    float scale = (z == 0) ? (rsqrtf((float)DHEAD) * LOG2E) : 1.0f;
    __half* out = (z == 0) ? g_q : ((z == 1) ? g_k : g_v);
    int r0 = row0 + wrow + g;
    int r1 = r0 + 8;
#pragma unroll
    for (int nt = 0; nt < 8; nt++) {
        int col = ncol0 + nt * 8 + qc * 2;
        int hh = col / DHEAD;
        int d = col - hh * DHEAD;
        if (r0 < rows) {
            out[((size_t)hh * rows + r0) * DPAD + d]     = __float2half(acc[nt][0] * scale);
            out[((size_t)hh * rows + r0) * DPAD + d + 1] = __float2half(acc[nt][1] * scale);
        }
        if (r1 < rows) {
            out[((size_t)hh * rows + r1) * DPAD + d]     = __float2half(acc[nt][2] * scale);
            out[((size_t)hh * rows + r1) * DPAD + d + 1] = __float2half(acc[nt][3] * scale);
        }
    }
}

// ---------------- kernel 3: flash attention, double-buffered, exp2 ----------------
__global__ void __launch_bounds__(256) flash_kernel() {
    __shared__ __half sQ[128 * 56];
    __shared__ __half sK[2][64 * 56];
    __shared__ __half sV[2][64 * 56];

    int qb = blockIdx.x, h = blockIdx.y;
    int q0 = qb * 128;
    int tid = threadIdx.x;
    int w = tid >> 5, lane = tid & 31;
    int g = lane >> 2, qc = lane & 3;

    const __half* qg = g_q + (size_t)h * L_Q * DPAD;
    const __half* kg = g_k + (size_t)h * L_CTX * DPAD;
    const __half* vg = g_v + (size_t)h * L_CTX * DPAD;

    for (int idx = tid; idx < 128 * 6; idx += 256) {
        int r = idx / 6, p = idx - r * 6;
        *(uint4*)&sQ[r * 56 + p * 8] =
            *(const uint4*)&qg[(size_t)(q0 + r) * DPAD + p * 8];
    }

    // prefetch registers for tile 0
    uint4 kr[2], vr[2];
    int pid0 = tid, pid1 = tid + 256;          // 384 uint4 per tile
    int pr0 = pid0 / 6, pp0 = pid0 - pr0 * 6;
    int pr1 = pid1 / 6, pp1 = pid1 - pr1 * 6;
    bool pv1 = pid1 < 384;
    {
        size_t go0 = (size_t)(1 + pr0) * DPAD + pp0 * 8;
        kr[0] = *(const uint4*)&kg[go0];
        vr[0] = *(const uint4*)&vg[go0];
        if (pv1) {
            size_t go1 = (size_t)(1 + pr1) * DPAD + pp1 * 8;
            kr[1] = *(const uint4*)&kg[go1];
            vr[1] = *(const uint4*)&vg[go1];
        }
    }
    *(uint4*)&sK[0][pr0 * 56 + pp0 * 8] = kr[0];
    *(uint4*)&sV[0][pr0 * 56 + pp0 * 8] = vr[0];
    if (pv1) {
        *(uint4*)&sK[0][pr1 * 56 + pp1 * 8] = kr[1];
        *(uint4*)&sV[0][pr1 * 56 + pp1 * 8] = vr[1];
    }
    __syncthreads();

    // Q A-fragments
    uint32_t aQ[3][4];
    uint32_t sQb = (uint32_t)__cvta_generic_to_shared(sQ);
    int wrow = w * 16;
#pragma unroll
    for (int kk = 0; kk < 3; kk++) {
        uint32_t addr = sQb +
            (uint32_t)(((wrow + (lane & 15)) * 56 + kk * 16 + ((lane >> 4) << 3)) * 2);
        ldsm4(aQ[kk], addr);
    }

    int r0 = wrow + g;
    int r1 = r0 + 8;

    // softmax init from register token (q pre-scaled by scale*log2e)
    float m0 = 0.f, m1 = 0.f;
#pragma unroll
    for (int d = 0; d < DHEAD; d++) {
        float kd = __half2float(kg[d]);
        m0 += __half2float(qg[(size_t)(q0 + r0) * DPAD + d]) * kd;
        m1 += __half2float(qg[(size_t)(q0 + r1) * DPAD + d]) * kd;
    }
    float l0 = 1.f, l1 = 1.f;

    float o[5][4];
#pragma unroll
    for (int v = 0; v < 5; v++) {
        float v0 = __half2float(vg[v * 8 + qc * 2]);
        float v1 = __half2float(vg[v * 8 + qc * 2 + 1]);
        o[v][0] = v0; o[v][1] = v1; o[v][2] = v0; o[v][3] = v1;
    }

    const unsigned long long* mr0 =
        (const unsigned long long*)(g_mbits + (size_t)(q0 + r0) * 128);
    const unsigned long long* mr1 =
        (const unsigned long long*)(g_mbits + (size_t)(q0 + r1) * 128);

    uint32_t sK0 = (uint32_t)__cvta_generic_to_shared(&sK[0][0]);
    uint32_t sV0 = (uint32_t)__cvta_generic_to_shared(&sV[0][0]);
    const uint32_t BUFB = 64 * 56 * 2;   // bytes per buffer

    int cur = 0;
    for (int t = 0; t < 64; t++) {
        // prefetch next tile into registers
        if (t < 63) {
            int k0n = (t + 1) * 64;
            size_t go0 = (size_t)(1 + k0n + pr0) * DPAD + pp0 * 8;
            kr[0] = *(const uint4*)&kg[go0];
            vr[0] = *(const uint4*)&vg[go0];
            if (pv1) {
                size_t go1 = (size_t)(1 + k0n + pr1) * DPAD + pp1 * 8;
                kr[1] = *(const uint4*)&kg[go1];
                vr[1] = *(const uint4*)&vg[go1];
            }
        }

        uint32_t sKb = sK0 + cur * BUFB;
        uint32_t sVb = sV0 + cur * BUFB;

        // ---- S = Q K^T ----
        float s[8][4] = {};
#pragma unroll
        for (int kk = 0; kk < 3; kk++) {
#pragma unroll
            for (int pr = 0; pr < 4; pr++) {
                uint32_t b[4];
                uint32_t addr = sKb +
                    (uint32_t)(((pr * 16 + (lane & 15)) * 56 + kk * 16 + ((lane >> 4) << 3)) * 2);
                ldsm4(b, addr);
                uint32_t b0[2] = {b[0], b[2]};
                uint32_t b1[2] = {b[1], b[3]};
                mma16816(s[2 * pr],     aQ[kk], b0);
                mma16816(s[2 * pr + 1], aQ[kk], b1);
            }
        }

        // ---- mask + online softmax (base-2 exponentials) ----
        unsigned long long mb0 = mr0[t], mb1 = mr1[t];
        float mx0 = -1e30f, mx1 = -1e30f;
#pragma unroll
        for (int v = 0; v < 8; v++) {
            int c = v * 8 + qc * 2;
            s[v][0] = ((mb0 >> c) & 1ull)       ? s[v][0] : -1e30f;
            s[v][1] = ((mb0 >> (c + 1)) & 1ull) ? s[v][1] : -1e30f;
            s[v][2] = ((mb1 >> c) & 1ull)       ? s[v][2] : -1e30f;
            s[v][3] = ((mb1 >> (c + 1)) & 1ull) ? s[v][3] : -1e30f;
            mx0 = fmaxf(mx0, fmaxf(s[v][0], s[v][1]));
            mx1 = fmaxf(mx1, fmaxf(s[v][2], s[v][3]));
        }
        mx0 = fmaxf(mx0, __shfl_xor_sync(0xffffffffu, mx0, 1));
        mx0 = fmaxf(mx0, __shfl_xor_sync(0xffffffffu, mx0, 2));
        mx1 = fmaxf(mx1, __shfl_xor_sync(0xffffffffu, mx1, 1));
        mx1 = fmaxf(mx1, __shfl_xor_sync(0xffffffffu, mx1, 2));

        float mn0 = fmaxf(m0, mx0), mn1 = fmaxf(m1, mx1);
        float c0 = ex2(m0 - mn0), c1 = ex2(m1 - mn1);
        float sum0 = 0.f, sum1 = 0.f;
#pragma unroll
        for (int v = 0; v < 8; v++) {
            s[v][0] = ex2(s[v][0] - mn0);
            s[v][1] = ex2(s[v][1] - mn0);
            s[v][2] = ex2(s[v][2] - mn1);
            s[v][3] = ex2(s[v][3] - mn1);
            sum0 += s[v][0] + s[v][1];
            sum1 += s[v][2] + s[v][3];
        }
        sum0 += __shfl_xor_sync(0xffffffffu, sum0, 1);
        sum0 += __shfl_xor_sync(0xffffffffu, sum0, 2);
        sum1 += __shfl_xor_sync(0xffffffffu, sum1, 1);
        sum1 += __shfl_xor_sync(0xffffffffu, sum1, 2);
        l0 = l0 * c0 + sum0;
        l1 = l1 * c1 + sum1;
        m0 = mn0; m1 = mn1;

#pragma unroll
        for (int v = 0; v < 5; v++) {
            o[v][0] *= c0; o[v][1] *= c0; o[v][2] *= c1; o[v][3] *= c1;
        }

        uint32_t pa[4][4];
#pragma unroll
        for (int kk = 0; kk < 4; kk++) {
            int v0 = 2 * kk, v1 = 2 * kk + 1;
            pa[kk][0] = pack_half2(s[v0][0], s[v0][1]);
            pa[kk][1] = pack_half2(s[v0][2], s[v0][3]);
            pa[kk][2] = pack_half2(s[v1][0], s[v1][1]);
            pa[kk][3] = pack_half2(s[v1][2], s[v1][3]);
        }

        // ---- O += P V ----
#pragma unroll
        for (int kk = 0; kk < 4; kk++) {
#pragma unroll
            for (int v = 0; v < 5; v++) {
                uint32_t b[2];
                uint32_t addr = sVb +
                    (uint32_t)(((kk * 16 + (lane & 15)) * 56 + v * 8) * 2);
                ldsm2t(b, addr);
                mma16816(o[v], pa[kk], b);
            }
        }

        // write prefetched tile to the other buffer
        if (t < 63) {
            int nb = cur ^ 1;
            *(uint4*)&sK[nb][pr0 * 56 + pp0 * 8] = kr[0];
            *(uint4*)&sV[nb][pr0 * 56 + pp0 * 8] = vr[0];
            if (pv1) {
                *(uint4*)&sK[nb][pr1 * 56 + pp1 * 8] = kr[1];
                *(uint4*)&sV[nb][pr1 * 56 + pp1 * 8] = vr[1];
            }
        }
        __syncthreads();
        cur ^= 1;
    }

    // ---- epilogue: normalize, split to fp16 hi/lo ----
    float inv0 = 1.f / l0, inv1 = 1.f / l1;
    __half* ogh = g_oh + (size_t)q0 * C_DIM + h * DHEAD;
    __half* ogl = g_ol + (size_t)q0 * C_DIM + h * DHEAD;
#pragma unroll
    for (int v = 0; v < 5; v++) {
        int n = v * 8 + qc * 2;
        float f00 = o[v][0] * inv0, f01 = o[v][1] * inv0;
        float f10 = o[v][2] * inv1, f11 = o[v][3] * inv1;
        __half h00, l00, h01, l01, h10, l10, h11, l11;
        split_h(f00, h00, l00); split_h(f01, h01, l01);
        split_h(f10, h10, l10); split_h(f11, h11, l11);
        *(__half2*)&ogh[(size_t)r0 * C_DIM + n] = __halves2half2(h00, h01);
        *(__half2*)&ogl[(size_t)r0 * C_DIM + n] = __halves2half2(l00, l01);
        *(__half2*)&ogh[(size_t)r1 * C_DIM + n] = __halves2half2(h10, h11);
        *(__half2*)&ogl[(size_t)r1 * C_DIM + n] = __halves2half2(l10, l11);
    }
}

// ---------------- kernel 4: output projection, fp16 HMMA, k-chunk 32 ----------------
__global__ void __launch_bounds__(256) out_hmma_kernel(const float* __restrict__ bo,
                                                       float* __restrict__ out) {
    __shared__ __half sAh[128 * 40], sAl[128 * 40];
    __shared__ __half sBh[32 * 72],  sBl[32 * 72];

    int row0 = blockIdx.x * 128;
    int ncol0 = blockIdx.y * 64;

    int tid = threadIdx.x;
    int w = tid >> 5, lane = tid & 31;
    int g = lane >> 2, qc = lane & 3;
    int wrow = w * 16;

    uint32_t sAhb = (uint32_t)__cvta_generic_to_shared(sAh);
    uint32_t sAlb = (uint32_t)__cvta_generic_to_shared(sAl);
    uint32_t sBhb = (uint32_t)__cvta_generic_to_shared(sBh);
    uint32_t sBlb = (uint32_t)__cvta_generic_to_shared(sBl);

    float acc[8][4] = {};

    for (int k0 = 0; k0 < C_DIM; k0 += 32) {
        __syncthreads();
        // A tile: 128 x 32 (hi+lo): 512 uint4
#pragma unroll
        for (int i = 0; i < 2; i++) {
            int id = tid + i * 256;
            int r = id >> 2, c = (id & 3) * 8;
            size_t off = (size_t)(row0 + r) * C_DIM + k0 + c;
            *(uint4*)&sAh[r * 40 + c] = *(const uint4*)&g_oh[off];
            *(uint4*)&sAl[r * 40 + c] = *(const uint4*)&g_ol[off];
        }
        // B tile: 32 x 64 = 256 uint4, one pass
        {
            int r = tid >> 3, c = (tid & 7) * 8;
            size_t off = (size_t)3 * WSZ + (size_t)(k0 + r) * C_DIM + ncol0 + c;
            *(uint4*)&sBh[r * 72 + c] = *(const uint4*)&g_w_h[off];
            *(uint4*)&sBl[r * 72 + c] = *(const uint4*)&g_w_l[off];
        }
        __syncthreads();

#pragma unroll
        for (int kk = 0; kk < 2; kk++) {
            uint32_t ah[4], al[4];
            uint32_t aoff = (uint32_t)(((wrow + (lane & 15)) * 40 + kk * 16 + ((lane >> 4) << 3)) * 2);
            ldsm4(ah, sAhb + aoff);
            ldsm4(al, sAlb + aoff);
#pragma unroll
            for (int nt = 0; nt < 8; nt++) {
                uint32_t bh[2], bl[2];
                uint32_t boff = (uint32_t)(((kk * 16 + (lane & 15)) * 72 + nt * 8) * 2);
                ldsm2t(bh, sBhb + boff);
                ldsm2t(bl, sBlb + boff);
                mma16816(acc[nt], ah, bh);
                mma16816(acc[nt], ah, bl);
                mma16816(acc[nt], al, bh);
            }
        }
    }

    int r0 = row0 + wrow + g;
    int r1 = r0 + 8;
    int p0 = (r0 & 255) * 16 + (r0 >> 8);   // (B H W) T permutation
    int p1 = (r1 & 255) * 16 + (r1 >> 8);
#pragma unroll
    for (int nt = 0; nt < 8; nt++) {
        int col = ncol0 + nt * 8 + qc * 2;
        float b0 = bo[col], b1 = bo[col + 1];
        *(float2*)&out[(size_t)p0 * C_DIM + col] =
            make_float2(acc[nt][0] + b0, acc[nt][1] + b1);
        *(float2*)&out[(size_t)p1 * C_DIM + col] =
            make_float2(acc[nt][2] + b0, acc[nt][3] + b1);
    }
}

// ---------------- launch ----------------
extern "C" void kernel_launch(void* const* d_in, const int* in_sizes, int n_in,
                              void* d_out, int out_size) {
    const float* feat         = (const float*)d_in[0];
    const unsigned char* mask = (const unsigned char*)d_in[1];
    const float* Wq           = (const float*)d_in[2];
    const float* Wk           = (const float*)d_in[3];
    const float* Wv           = (const float*)d_in[4];
    const float* reg          = (const float*)d_in[5];
    const float* Wo           = (const float*)d_in[6];
    const float* bo           = (const float*)d_in[7];
    float* out                = (float*)d_out;

    (void)in_sizes; (void)n_in; (void)out_size;

    detect_mask_kernel<<<1, 256>>>(mask);
    pack_mask_kernel<<<(L_Q * 4096) / 256, 256>>>(mask);
    split_w_kernel<<<dim3(WSZ / 256, 4), 256>>>(Wq, Wk, Wv, Wo);
    build_ctx_kernel<<<dim3(10, 8, 16), dim3(32, 8)>>>(feat, reg);
    qkv_hmma_kernel<<<dim3(33, 15), 256>>>();
    flash_kernel<<<dim3(32, N_HEADS), 256>>>();
    out_hmma_kernel<<<dim3(32, 5), 256>>>(bo, out);
}

// round 7
// speedup vs baseline: 1.9298x; 1.9298x over previous
#include <cuda_runtime.h>
#include <cuda_fp16.h>
#include <cstdint>

#define L_Q   4096
#define L_CTX 4097
#define C_DIM 320
#define N_HEADS 8
#define DHEAD 40
#define DPAD  48
#define WSZ   (C_DIM * C_DIM)   // 102400

// ---------------- device scratch (no allocations allowed) ----------------
__device__ __half g_ctx_h[(size_t)L_CTX * C_DIM];
__device__ __half g_ctx_l[(size_t)L_CTX * C_DIM];
__device__ __half g_w_h[4 * WSZ];
__device__ __half g_w_l[4 * WSZ];
__device__ __half g_q[(size_t)N_HEADS * L_Q * DPAD];    // d 40..47 zero
__device__ __half g_k[(size_t)N_HEADS * L_CTX * DPAD];
__device__ __half g_v[(size_t)N_HEADS * L_CTX * DPAD];  // d 40 set to 1.0 (l column)
__device__ __half g_oh[(size_t)L_Q * C_DIM];
__device__ __half g_ol[(size_t)L_Q * C_DIM];
__device__ __half g_mbias[(size_t)L_Q * 4096];          // 0 or -1024 per mask bit
__device__ int    g_mask_is_u8;

#define LOG2E 1.4426950408889634f

// ---------------- helpers ----------------
__device__ __forceinline__ void mma16816(float* d, const uint32_t* a, const uint32_t* b) {
    asm volatile(
        "mma.sync.aligned.m16n8k16.row.col.f32.f16.f16.f32 "
        "{%0,%1,%2,%3}, {%4,%5,%6,%7}, {%8,%9}, {%0,%1,%2,%3};"
        : "+f"(d[0]), "+f"(d[1]), "+f"(d[2]), "+f"(d[3])
        : "r"(a[0]), "r"(a[1]), "r"(a[2]), "r"(a[3]), "r"(b[0]), "r"(b[1]));
}
__device__ __forceinline__ void mma16816_f16(uint32_t* d, const uint32_t* a, const uint32_t* b) {
    asm volatile(
        "mma.sync.aligned.m16n8k16.row.col.f16.f16.f16.f16 "
        "{%0,%1}, {%2,%3,%4,%5}, {%6,%7}, {%0,%1};"
        : "+r"(d[0]), "+r"(d[1])
        : "r"(a[0]), "r"(a[1]), "r"(a[2]), "r"(a[3]), "r"(b[0]), "r"(b[1]));
}
__device__ __forceinline__ void ldsm4(uint32_t* r, uint32_t saddr) {
    asm volatile("ldmatrix.sync.aligned.m8n8.x4.shared.b16 {%0,%1,%2,%3}, [%4];"
                 : "=r"(r[0]), "=r"(r[1]), "=r"(r[2]), "=r"(r[3]) : "r"(saddr));
}
__device__ __forceinline__ void ldsm2t(uint32_t* r, uint32_t saddr) {
    asm volatile("ldmatrix.sync.aligned.m8n8.x2.trans.shared.b16 {%0,%1}, [%2];"
                 : "=r"(r[0]), "=r"(r[1]) : "r"(saddr));
}
__device__ __forceinline__ void split_h(float v, __half& h, __half& l) {
    h = __float2half_rn(v);
    l = __float2half_rn(v - __half2float(h));
}
__device__ __forceinline__ float ex2f(float x) {
    float y;
    asm("ex2.approx.f32 %0, %1;" : "=f"(y) : "f"(x));
    return y;
}
__device__ __forceinline__ uint32_t hexp2_u(uint32_t x) {
    uint32_t y;
    asm("ex2.approx.f16x2 %0, %1;" : "=r"(y) : "r"(x));
    return y;
}
__device__ __forceinline__ __half2 u2h(uint32_t u) { return *(__half2*)&u; }
__device__ __forceinline__ uint32_t h2u(__half2 h) { return *(uint32_t*)&h; }
__device__ __forceinline__ void cp_async16(uint32_t dst, const void* src) {
    asm volatile("cp.async.cg.shared.global [%0], [%1], 16;" :: "r"(dst), "l"(src));
}

// ---------------- kernel 0: detect mask dtype ----------------
__global__ void detect_mask_kernel(const unsigned char* __restrict__ mask) {
    __shared__ int cnt[256];
    int tid = threadIdx.x;
    int c = 0;
    for (int i = tid; i < 4096; i += 256) c += (mask[i] != 0);
    cnt[tid] = c;
    __syncthreads();
    for (int s = 128; s; s >>= 1) {
        if (tid < s) cnt[tid] += cnt[tid + s];
        __syncthreads();
    }
    if (tid == 0) g_mask_is_u8 = (cnt[0] > 1024) ? 1 : 0;
}

// ---------------- kernel 0b: mask -> fp16 additive bias (0 / -1024) ----------------
__global__ void pack_bias_kernel(const void* __restrict__ mask) {
    size_t base = ((size_t)blockIdx.x * 256 + threadIdx.x) * 4;
    int v0, v1, v2, v3;
    if (g_mask_is_u8) {
        uchar4 m = *(const uchar4*)((const unsigned char*)mask + base);
        v0 = m.x; v1 = m.y; v2 = m.z; v3 = m.w;
    } else {
        int4 m = *(const int4*)((const int*)mask + base);
        v0 = m.x; v1 = m.y; v2 = m.z; v3 = m.w;
    }
    const __half Z = __float2half(0.f), NEG = __float2half(-1024.f);
    __half2 a = __halves2half2(v0 ? Z : NEG, v1 ? Z : NEG);
    __half2 b = __halves2half2(v2 ? Z : NEG, v3 ? Z : NEG);
    uint2 w = make_uint2(h2u(a), h2u(b));
    *(uint2*)&g_mbias[base] = w;
}

// ---------------- kernel 0c: split weights ----------------
__global__ void split_w_kernel(const float* __restrict__ Wq, const float* __restrict__ Wk,
                               const float* __restrict__ Wv, const float* __restrict__ Wo) {
    int which = blockIdx.y;
    const float* W = (which == 0) ? Wq : (which == 1) ? Wk : (which == 2) ? Wv : Wo;
    int idx = blockIdx.x * 256 + threadIdx.x;
    float v = W[idx];
    __half h, l;
    split_h(v, h, l);
    g_w_h[which * WSZ + idx] = h;
    g_w_l[which * WSZ + idx] = l;
}

// ---------------- kernel 0d: V ones column (l accumulator) ----------------
__global__ void v_ones_kernel() {
    int idx = blockIdx.x * 256 + threadIdx.x;
    if (idx < N_HEADS * L_CTX)
        g_v[(size_t)idx * DPAD + 40] = __float2half(1.0f);
}

// ---------------- kernel 1: build context ----------------
__global__ void build_ctx_kernel(const float* __restrict__ feat,
                                 const float* __restrict__ reg) {
    __shared__ float tile[32][33];
    int c0 = blockIdx.x * 32, x0 = blockIdx.y * 32, t = blockIdx.z;
    if (blockIdx.x == 0 && blockIdx.y == 0 && t == 0) {
        int lt = threadIdx.y * 32 + threadIdx.x;
        for (int c = lt; c < C_DIM; c += 256) {
            __half h, l;
            split_h(reg[c], h, l);
            g_ctx_h[c] = h;
            g_ctx_l[c] = l;
        }
    }
#pragma unroll
    for (int j = 0; j < 32; j += 8)
        tile[threadIdx.y + j][threadIdx.x] =
            feat[((size_t)(t * C_DIM + c0 + threadIdx.y + j)) * 256 + x0 + threadIdx.x];
    __syncthreads();
#pragma unroll
    for (int j = 0; j < 32; j += 8) {
        float v = tile[threadIdx.x][threadIdx.y + j];
        __half h, l;
        split_h(v, h, l);
        size_t off = (size_t)(1 + t * 256 + x0 + threadIdx.y + j) * C_DIM + c0 + threadIdx.x;
        g_ctx_h[off] = h;
        g_ctx_l[off] = l;
    }
}

// ---------------- kernel 2: fused QKV projection, fp16 HMMA ----------------
__global__ void __launch_bounds__(256) qkv_hmma_kernel() {
    __shared__ __half sAh[128 * 40], sAl[128 * 40];
    __shared__ __half sBh[32 * 72],  sBl[32 * 72];

    int by = blockIdx.y;
    int z = by / 5;
    int rows = (z == 0) ? L_Q : L_CTX;
    int ashift = (z == 0) ? 1 : 0;
    int row0 = blockIdx.x * 128;
    if (row0 >= rows) return;
    int ncol0 = (by % 5) * 64;

    int tid = threadIdx.x;
    int w = tid >> 5, lane = tid & 31;
    int g = lane >> 2, qc = lane & 3;
    int wrow = w * 16;

    uint32_t sAhb = (uint32_t)__cvta_generic_to_shared(sAh);
    uint32_t sAlb = (uint32_t)__cvta_generic_to_shared(sAl);
    uint32_t sBhb = (uint32_t)__cvta_generic_to_shared(sBh);
    uint32_t sBlb = (uint32_t)__cvta_generic_to_shared(sBl);

    float acc[8][4] = {};

    for (int k0 = 0; k0 < C_DIM; k0 += 32) {
        __syncthreads();
#pragma unroll
        for (int i = 0; i < 2; i++) {
            int id = tid + i * 256;
            int r = id >> 2, c = (id & 3) * 8;
            uint4 vh = make_uint4(0, 0, 0, 0), vl = vh;
            if (row0 + r < rows) {
                size_t off = (size_t)(row0 + r + ashift) * C_DIM + k0 + c;
                vh = *(const uint4*)&g_ctx_h[off];
                vl = *(const uint4*)&g_ctx_l[off];
            }
            *(uint4*)&sAh[r * 40 + c] = vh;
            *(uint4*)&sAl[r * 40 + c] = vl;
        }
        {
            int r = tid >> 3, c = (tid & 7) * 8;
            size_t off = (size_t)z * WSZ + (size_t)(k0 + r) * C_DIM + ncol0 + c;
            *(uint4*)&sBh[r * 72 + c] = *(const uint4*)&g_w_h[off];
            *(uint4*)&sBl[r * 72 + c] = *(const uint4*)&g_w_l[off];
        }
        __syncthreads();

#pragma unroll
        for (int kk = 0; kk < 2; kk++) {
            uint32_t ah[4], al[4];
            uint32_t aoff = (uint32_t)(((wrow + (lane & 15)) * 40 + kk * 16 + ((lane >> 4) << 3)) * 2);
            ldsm4(ah, sAhb + aoff);
            ldsm4(al, sAlb + aoff);
#pragma unroll
            for (int nt = 0; nt < 8; nt++) {
                uint32_t bh[2], bl[2];
                uint32_t boff = (uint32_t)(((kk * 16 + (lane & 15)) * 72 + nt * 8) * 2);
                ldsm2t(bh, sBhb + boff);
                ldsm2t(bl, sBlb + boff);
                mma16816(acc[nt], ah, bh);
                mma16816(acc[nt], ah, bl);
                mma16816(acc[nt], al, bh);
            }
        }
    }

    float scale = (z == 0) ? (rsqrtf((float)DHEAD) * LOG2E) : 1.0f;
    __half* out = (z == 0) ? g_q : ((z == 1) ? g_k : g_v);
    int r0 = row0 + wrow + g;
    int r1 = r0 + 8;
#pragma unroll
    for (int nt = 0; nt < 8; nt++) {
        int col = ncol0 + nt * 8 + qc * 2;
        int hh = col / DHEAD;
        int d = col - hh * DHEAD;
        if (r0 < rows) {
            out[((size_t)hh * rows + r0) * DPAD + d]     = __float2half(acc[nt][0] * scale);
            out[((size_t)hh * rows + r0) * DPAD + d + 1] = __float2half(acc[nt][1] * scale);
        }
        if (r1 < rows) {
            out[((size_t)hh * rows + r1) * DPAD + d]     = __float2half(acc[nt][2] * scale);
            out[((size_t)hh * rows + r1) * DPAD + d + 1] = __float2half(acc[nt][3] * scale);
        }
    }
}

// ---------------- kernel 3: flash attention, f16-S + bias-mask + l-in-mma ----------------
__global__ void __launch_bounds__(256, 2) flash_kernel() {
    __shared__ __half sQ[128 * 56];
    __shared__ __half sK[2][64 * 56];
    __shared__ __half sV[2][64 * 56];

    int qb = blockIdx.x, h = blockIdx.y;
    int q0 = qb * 128;
    int tid = threadIdx.x;
    int w = tid >> 5, lane = tid & 31;
    int g = lane >> 2, qc = lane & 3;

    const __half* qg = g_q + (size_t)h * L_Q * DPAD;
    const __half* kg = g_k + (size_t)h * L_CTX * DPAD;
    const __half* vg = g_v + (size_t)h * L_CTX * DPAD;

    uint32_t sK0 = (uint32_t)__cvta_generic_to_shared(&sK[0][0]);
    uint32_t sV0 = (uint32_t)__cvta_generic_to_shared(&sV[0][0]);
    const uint32_t BUFB = 64 * 56 * 2;

    // cp.async tile 0 into buffer 0  (768 chunks of 16B: K 0..383, V 384..767)
    {
#pragma unroll
        for (int i = 0; i < 3; i++) {
            int id = tid + i * 256;
            int cid = (id < 384) ? id : id - 384;
            int r = cid / 6, p = cid - r * 6;
            const __half* src = (id < 384) ? kg : vg;
            uint32_t dstb = (id < 384) ? sK0 : sV0;
            cp_async16(dstb + (uint32_t)((r * 56 + p * 8) * 2),
                       src + (size_t)(1 + r) * DPAD + p * 8);
        }
        asm volatile("cp.async.commit_group;");
    }

    // Q tile (regular stores)
    for (int idx = tid; idx < 128 * 6; idx += 256) {
        int r = idx / 6, p = idx - r * 6;
        *(uint4*)&sQ[r * 56 + p * 8] =
            *(const uint4*)&qg[(size_t)(q0 + r) * DPAD + p * 8];
    }
    __syncthreads();

    uint32_t aQ[3][4];
    uint32_t sQb = (uint32_t)__cvta_generic_to_shared(sQ);
    int wrow = w * 16;
#pragma unroll
    for (int kk = 0; kk < 3; kk++) {
        uint32_t addr = sQb +
            (uint32_t)(((wrow + (lane & 15)) * 56 + kk * 16 + ((lane >> 4) << 3)) * 2);
        ldsm4(aQ[kk], addr);
    }

    int r0 = wrow + g;
    int r1 = r0 + 8;

    // softmax init from register token (q pre-scaled by scale*log2e)
    float m0 = 0.f, m1 = 0.f;
#pragma unroll
    for (int d = 0; d < DHEAD; d++) {
        float kd = __half2float(kg[d]);
        m0 += __half2float(qg[(size_t)(q0 + r0) * DPAD + d]) * kd;
        m1 += __half2float(qg[(size_t)(q0 + r1) * DPAD + d]) * kd;
    }

    // O accum: 6 n-tiles (cols 0..47); tile 5 col 40 = l (v_reg col40 = 1 -> l init 1)
    float o[6][4];
#pragma unroll
    for (int v = 0; v < 6; v++) {
        float v0 = __half2float(vg[v * 8 + qc * 2]);
        float v1 = __half2float(vg[v * 8 + qc * 2 + 1]);
        o[v][0] = v0; o[v][1] = v1; o[v][2] = v0; o[v][3] = v1;
    }

    const __half* mb0 = g_mbias + (size_t)(q0 + r0) * 4096;
    const __half* mb1 = g_mbias + (size_t)(q0 + r1) * 4096;

    int cur = 0;
    for (int t = 0; t < 64; t++) {
        int k0 = t * 64;

        // bias fragments (accumulator init): half2 per (row, n-tile)
        uint32_t bias0[8], bias1[8];
#pragma unroll
        for (int v = 0; v < 8; v++) {
            int c = k0 + v * 8 + qc * 2;
            bias0[v] = *(const uint32_t*)&mb0[c];
            bias1[v] = *(const uint32_t*)&mb1[c];
        }

        asm volatile("cp.async.wait_group 0;");
        __syncthreads();

        // prefetch next tile into other buffer
        if (t < 63) {
            int k0n = k0 + 64;
            uint32_t ob = (cur ^ 1) * BUFB;
#pragma unroll
            for (int i = 0; i < 3; i++) {
                int id = tid + i * 256;
                int cid = (id < 384) ? id : id - 384;
                int r = cid / 6, p = cid - r * 6;
                const __half* src = (id < 384) ? kg : vg;
                uint32_t dstb = ((id < 384) ? sK0 : sV0) + ob;
                cp_async16(dstb + (uint32_t)((r * 56 + p * 8) * 2),
                           src + (size_t)(1 + k0n + r) * DPAD + p * 8);
            }
            asm volatile("cp.async.commit_group;");
        }

        uint32_t sKb = sK0 + cur * BUFB;
        uint32_t sVb = sV0 + cur * BUFB;

        // ---- S = bias + Q K^T  (f16 accumulators) ----
        uint32_t sd[8][2];
#pragma unroll
        for (int v = 0; v < 8; v++) { sd[v][0] = bias0[v]; sd[v][1] = bias1[v]; }
#pragma unroll
        for (int kk = 0; kk < 3; kk++) {
#pragma unroll
            for (int pr = 0; pr < 4; pr++) {
                uint32_t b[4];
                uint32_t addr = sKb +
                    (uint32_t)(((pr * 16 + (lane & 15)) * 56 + kk * 16 + ((lane >> 4) << 3)) * 2);
                ldsm4(b, addr);
                uint32_t b0[2] = {b[0], b[2]};
                uint32_t b1[2] = {b[1], b[3]};
                mma16816_f16(sd[2 * pr],     aQ[kk], b0);
                mma16816_f16(sd[2 * pr + 1], aQ[kk], b1);
            }
        }

        // ---- online softmax (f16) ----
        __half2 mx2_0 = u2h(sd[0][0]);
        __half2 mx2_1 = u2h(sd[0][1]);
#pragma unroll
        for (int v = 1; v < 8; v++) {
            mx2_0 = __hmax2(mx2_0, u2h(sd[v][0]));
            mx2_1 = __hmax2(mx2_1, u2h(sd[v][1]));
        }
        float mx0 = fmaxf(__half2float(__low2half(mx2_0)), __half2float(__high2half(mx2_0)));
        float mx1 = fmaxf(__half2float(__low2half(mx2_1)), __half2float(__high2half(mx2_1)));
        mx0 = fmaxf(mx0, __shfl_xor_sync(0xffffffffu, mx0, 1));
        mx0 = fmaxf(mx0, __shfl_xor_sync(0xffffffffu, mx0, 2));
        mx1 = fmaxf(mx1, __shfl_xor_sync(0xffffffffu, mx1, 1));
        mx1 = fmaxf(mx1, __shfl_xor_sync(0xffffffffu, mx1, 2));

        float mn0 = fmaxf(m0, mx0), mn1 = fmaxf(m1, mx1);
        bool changed = !__all_sync(0xffffffffu, (mn0 == m0) && (mn1 == m1));
        if (changed) {
            float c0 = ex2f(m0 - mn0), c1 = ex2f(m1 - mn1);
#pragma unroll
            for (int v = 0; v < 6; v++) {
                o[v][0] *= c0; o[v][1] *= c0; o[v][2] *= c1; o[v][3] *= c1;
            }
            m0 = mn0; m1 = mn1;
        }

        __half2 mn0h = __float2half2_rn(mn0);
        __half2 mn1h = __float2half2_rn(mn1);
#pragma unroll
        for (int v = 0; v < 8; v++) {
            sd[v][0] = hexp2_u(h2u(__hsub2(u2h(sd[v][0]), mn0h)));
            sd[v][1] = hexp2_u(h2u(__hsub2(u2h(sd[v][1]), mn1h)));
        }

        // ---- O += P V  (P fragments = sd regs directly) ----
#pragma unroll
        for (int kk = 0; kk < 4; kk++) {
            uint32_t pa[4] = {sd[2 * kk][0], sd[2 * kk][1],
                              sd[2 * kk + 1][0], sd[2 * kk + 1][1]};
#pragma unroll
            for (int v = 0; v < 6; v++) {
                uint32_t b[2];
                uint32_t addr = sVb +
                    (uint32_t)(((kk * 16 + (lane & 15)) * 56 + v * 8) * 2);
                ldsm2t(b, addr);
                mma16816(o[v], pa, b);
            }
        }

        cur ^= 1;
    }

    // ---- epilogue: l from o[5] col 40 (qc==0 lane), normalize, split hi/lo ----
    float l0 = __shfl_sync(0xffffffffu, o[5][0], lane & 28);
    float l1 = __shfl_sync(0xffffffffu, o[5][2], lane & 28);
    float inv0 = 1.f / l0, inv1 = 1.f / l1;
    __half* ogh = g_oh + (size_t)q0 * C_DIM + h * DHEAD;
    __half* ogl = g_ol + (size_t)q0 * C_DIM + h * DHEAD;
#pragma unroll
    for (int v = 0; v < 5; v++) {
        int n = v * 8 + qc * 2;
        float f00 = o[v][0] * inv0, f01 = o[v][1] * inv0;
        float f10 = o[v][2] * inv1, f11 = o[v][3] * inv1;
        __half h00, l00, h01, l01, h10, l10, h11, l11;
        split_h(f00, h00, l00); split_h(f01, h01, l01);
        split_h(f10, h10, l10); split_h(f11, h11, l11);
        *(__half2*)&ogh[(size_t)r0 * C_DIM + n] = __halves2half2(h00, h01);
        *(__half2*)&ogl[(size_t)r0 * C_DIM + n] = __halves2half2(l00, l01);
        *(__half2*)&ogh[(size_t)r1 * C_DIM + n] = __halves2half2(h10, h11);
        *(__half2*)&ogl[(size_t)r1 * C_DIM + n] = __halves2half2(l10, l11);
    }
}

// ---------------- kernel 4: output projection, fp16 HMMA ----------------
__global__ void __launch_bounds__(256) out_hmma_kernel(const float* __restrict__ bo,
                                                       float* __restrict__ out) {
    __shared__ __half sAh[128 * 40], sAl[128 * 40];
    __shared__ __half sBh[32 * 72],  sBl[32 * 72];

    int row0 = blockIdx.x * 128;
    int ncol0 = blockIdx.y * 64;

    int tid = threadIdx.x;
    int w = tid >> 5, lane = tid & 31;
    int g = lane >> 2, qc = lane & 3;
    int wrow = w * 16;

    uint32_t sAhb = (uint32_t)__cvta_generic_to_shared(sAh);
    uint32_t sAlb = (uint32_t)__cvta_generic_to_shared(sAl);
    uint32_t sBhb = (uint32_t)__cvta_generic_to_shared(sBh);
    uint32_t sBlb = (uint32_t)__cvta_generic_to_shared(sBl);

    float acc[8][4] = {};

    for (int k0 = 0; k0 < C_DIM; k0 += 32) {
        __syncthreads();
#pragma unroll
        for (int i = 0; i < 2; i++) {
            int id = tid + i * 256;
            int r = id >> 2, c = (id & 3) * 8;
            size_t off = (size_t)(row0 + r) * C_DIM + k0 + c;
            *(uint4*)&sAh[r * 40 + c] = *(const uint4*)&g_oh[off];
            *(uint4*)&sAl[r * 40 + c] = *(const uint4*)&g_ol[off];
        }
        {
            int r = tid >> 3, c = (tid & 7) * 8;
            size_t off = (size_t)3 * WSZ + (size_t)(k0 + r) * C_DIM + ncol0 + c;
            *(uint4*)&sBh[r * 72 + c] = *(const uint4*)&g_w_h[off];
            *(uint4*)&sBl[r * 72 + c] = *(const uint4*)&g_w_l[off];
        }
        __syncthreads();

#pragma unroll
        for (int kk = 0; kk < 2; kk++) {
            uint32_t ah[4], al[4];
            uint32_t aoff = (uint32_t)(((wrow + (lane & 15)) * 40 + kk * 16 + ((lane >> 4) << 3)) * 2);
            ldsm4(ah, sAhb + aoff);
            ldsm4(al, sAlb + aoff);
#pragma unroll
            for (int nt = 0; nt < 8; nt++) {
                uint32_t bh[2], bl[2];
                uint32_t boff = (uint32_t)(((kk * 16 + (lane & 15)) * 72 + nt * 8) * 2);
                ldsm2t(bh, sBhb + boff);
                ldsm2t(bl, sBlb + boff);
                mma16816(acc[nt], ah, bh);
                mma16816(acc[nt], ah, bl);
                mma16816(acc[nt], al, bh);
            }
        }
    }

    int r0 = row0 + wrow + g;
    int r1 = r0 + 8;
    int p0 = (r0 & 255) * 16 + (r0 >> 8);
    int p1 = (r1 & 255) * 16 + (r1 >> 8);
#pragma unroll
    for (int nt = 0; nt < 8; nt++) {
        int col = ncol0 + nt * 8 + qc * 2;
        float b0 = bo[col], b1 = bo[col + 1];
        *(float2*)&out[(size_t)p0 * C_DIM + col] =
            make_float2(acc[nt][0] + b0, acc[nt][1] + b1);
        *(float2*)&out[(size_t)p1 * C_DIM + col] =
            make_float2(acc[nt][2] + b0, acc[nt][3] + b1);
    }
}

// ---------------- launch ----------------
extern "C" void kernel_launch(void* const* d_in, const int* in_sizes, int n_in,
                              void* d_out, int out_size) {
    const float* feat         = (const float*)d_in[0];
    const unsigned char* mask = (const unsigned char*)d_in[1];
    const float* Wq           = (const float*)d_in[2];
    const float* Wk           = (const float*)d_in[3];
    const float* Wv           = (const float*)d_in[4];
    const float* reg          = (const float*)d_in[5];
    const float* Wo           = (const float*)d_in[6];
    const float* bo           = (const float*)d_in[7];
    float* out                = (float*)d_out;

    (void)in_sizes; (void)n_in; (void)out_size;

    detect_mask_kernel<<<1, 256>>>(mask);
    pack_bias_kernel<<<(L_Q * 4096) / 1024, 256>>>(mask);
    split_w_kernel<<<dim3(WSZ / 256, 4), 256>>>(Wq, Wk, Wv, Wo);
    build_ctx_kernel<<<dim3(10, 8, 16), dim3(32, 8)>>>(feat, reg);
    qkv_hmma_kernel<<<dim3(33, 15), 256>>>();
    v_ones_kernel<<<(N_HEADS * L_CTX + 255) / 256, 256>>>();
    flash_kernel<<<dim3(32, N_HEADS), 256>>>();
    out_hmma_kernel<<<dim3(32, 5), 256>>>(bo, out);
}